// round 5
// baseline (speedup 1.0000x reference)
#include <cuda_runtime.h>
#include <math.h>

#define HEADS 16
#define GROUPS 4
#define BATCH 2
#define SEQ 2048
#define DM 2048
#define DKV 512
#define HD 128
#define KD 2048

// Scratch (allocation-free rule: __device__ globals)
__device__ float g_q[BATCH * SEQ * DM];
__device__ float g_k[BATCH * SEQ * DKV];
__device__ float g_v[BATCH * SEQ * DKV];

// ---------------------------------------------------------------------------
// helpers
// ---------------------------------------------------------------------------
__device__ __forceinline__ unsigned f2tf(float f) {
    unsigned u;
    asm("cvt.rna.tf32.f32 %0, %1;" : "=r"(u) : "f"(f));
    return u;
}

__device__ __forceinline__ float fexp2(float x) {
    float r;
    asm("ex2.approx.f32 %0, %1;" : "=f"(r) : "f"(x));
    return r;
}

__device__ __forceinline__ void mma8(float c[4], const unsigned a[4],
                                     const unsigned b[2]) {
    asm volatile(
        "mma.sync.aligned.m16n8k8.row.col.f32.tf32.tf32.f32 "
        "{%0,%1,%2,%3}, {%4,%5,%6,%7}, {%8,%9}, {%0,%1,%2,%3};\n"
        : "+f"(c[0]), "+f"(c[1]), "+f"(c[2]), "+f"(c[3])
        : "r"(a[0]), "r"(a[1]), "r"(a[2]), "r"(a[3]), "r"(b[0]), "r"(b[1]));
}

__device__ __forceinline__ void ldmx4(unsigned r[4], const float* p) {
    unsigned addr = (unsigned)__cvta_generic_to_shared(p);
    asm volatile(
        "ldmatrix.sync.aligned.m8n8.x4.shared.b16 {%0,%1,%2,%3}, [%4];"
        : "=r"(r[0]), "=r"(r[1]), "=r"(r[2]), "=r"(r[3])
        : "r"(addr));
}

// ---------------------------------------------------------------------------
// Fused QKV projection GEMM, 2-stage double-buffered.
// CTA tile 128(m) x 256(n) x 32(k), 8 warps, warp tile 64x64, ldmatrix frags.
// ---------------------------------------------------------------------------
#define GLDA 36
#define GSTAGE (128 * GLDA + 256 * GLDA)       // floats per stage
#define GEMM_SMEM_FLOATS (2 * GSTAGE)

__global__ __launch_bounds__(256, 1) void gemm_qkv(const float* __restrict__ x,
                                                   const float* __restrict__ Wq,
                                                   const float* __restrict__ Wk,
                                                   const float* __restrict__ Wv) {
    extern __shared__ float gsm[];

    const int tid = threadIdx.x;
    const int w = tid >> 5;
    const int lane = tid & 31;
    const int lg = lane >> 2;
    const int t4 = lane & 3;
    const int wm = (w & 1) * 64;
    const int wn = (w >> 1) * 64;
    const int mBase = blockIdx.y * 128;
    const int nb = blockIdx.x;

    const float* W;
    float* C;
    int cN, nl0;
    if (nb < 8)       { W = Wq; C = g_q; cN = DM;  nl0 = nb * 256; }
    else if (nb < 10) { W = Wk; C = g_k; cN = DKV; nl0 = (nb - 8) * 256; }
    else              { W = Wv; C = g_v; cN = DKV; nl0 = (nb - 10) * 256; }

    float acc[4][8][4];
#pragma unroll
    for (int mt = 0; mt < 4; mt++)
#pragma unroll
        for (int nt = 0; nt < 8; nt++)
#pragma unroll
            for (int i = 0; i < 4; i++) acc[mt][nt][i] = 0.f;

    const int grow = tid >> 3;
    const int gcol = (tid & 7) * 4;

    const float* ap = x + (size_t)(mBase + grow) * KD + gcol;
    const float* wp = W + (size_t)(nl0 + grow) * KD + gcol;

    const int aRow = wm + ((lane >> 3) & 1) * 8 + (lane & 7);
    const int aCol = (lane >> 4) * 4;
    const int bRow = wn + ((lane >> 4) & 1) * 8 + (lane & 7);
    const int bCol = ((lane >> 3) & 1) * 4;

    float4 pa[4], pb[8];
    const int ktiles = KD / 32;

    // prologue: tile0 -> stage0, prefetch tile1
#pragma unroll
    for (int p = 0; p < 4; p++) pa[p] = *(const float4*)(ap + (size_t)p * 32 * KD);
#pragma unroll
    for (int p = 0; p < 8; p++) pb[p] = *(const float4*)(wp + (size_t)p * 32 * KD);
    {
        float* As = gsm;
        float* Bs = gsm + 128 * GLDA;
#pragma unroll
        for (int p = 0; p < 4; p++) {
            float4 va = pa[p];
            *(float4*)&As[(p * 32 + grow) * GLDA + gcol] =
                make_float4(__uint_as_float(f2tf(va.x)), __uint_as_float(f2tf(va.y)),
                            __uint_as_float(f2tf(va.z)), __uint_as_float(f2tf(va.w)));
        }
#pragma unroll
        for (int p = 0; p < 8; p++) {
            float4 vb = pb[p];
            *(float4*)&Bs[(p * 32 + grow) * GLDA + gcol] =
                make_float4(__uint_as_float(f2tf(vb.x)), __uint_as_float(f2tf(vb.y)),
                            __uint_as_float(f2tf(vb.z)), __uint_as_float(f2tf(vb.w)));
        }
    }
#pragma unroll
    for (int p = 0; p < 4; p++)
        pa[p] = *(const float4*)(ap + 32 + (size_t)p * 32 * KD);
#pragma unroll
    for (int p = 0; p < 8; p++)
        pb[p] = *(const float4*)(wp + 32 + (size_t)p * 32 * KD);
    __syncthreads();

    for (int kt = 0; kt < ktiles; kt++) {
        const float* As = gsm + (kt & 1) * GSTAGE;
        const float* Bs = As + 128 * GLDA;

#pragma unroll
        for (int ks = 0; ks < 4; ks++) {
            const int k0 = ks * 8;
            unsigned af[4][4], bf[4][4];
#pragma unroll
            for (int mt = 0; mt < 4; mt++)
                ldmx4(af[mt], &As[(aRow + mt * 16) * GLDA + k0 + aCol]);
#pragma unroll
            for (int ntp = 0; ntp < 4; ntp++)
                ldmx4(bf[ntp], &Bs[(bRow + ntp * 16) * GLDA + k0 + bCol]);
#pragma unroll
            for (int mt = 0; mt < 4; mt++)
#pragma unroll
                for (int nt = 0; nt < 8; nt++)
                    mma8(acc[mt][nt], af[mt], &bf[nt >> 1][(nt & 1) * 2]);
        }

        if (kt + 1 < ktiles) {
            float* An = gsm + ((kt + 1) & 1) * GSTAGE;
            float* Bn = An + 128 * GLDA;
#pragma unroll
            for (int p = 0; p < 4; p++) {
                float4 va = pa[p];
                *(float4*)&An[(p * 32 + grow) * GLDA + gcol] =
                    make_float4(__uint_as_float(f2tf(va.x)), __uint_as_float(f2tf(va.y)),
                                __uint_as_float(f2tf(va.z)), __uint_as_float(f2tf(va.w)));
            }
#pragma unroll
            for (int p = 0; p < 8; p++) {
                float4 vb = pb[p];
                *(float4*)&Bn[(p * 32 + grow) * GLDA + gcol] =
                    make_float4(__uint_as_float(f2tf(vb.x)), __uint_as_float(f2tf(vb.y)),
                                __uint_as_float(f2tf(vb.z)), __uint_as_float(f2tf(vb.w)));
            }
        }
        if (kt + 2 < ktiles) {
            const float* an = ap + (kt + 2) * 32;
            const float* wn2 = wp + (kt + 2) * 32;
#pragma unroll
            for (int p = 0; p < 4; p++)
                pa[p] = *(const float4*)(an + (size_t)p * 32 * KD);
#pragma unroll
            for (int p = 0; p < 8; p++)
                pb[p] = *(const float4*)(wn2 + (size_t)p * 32 * KD);
        }
        __syncthreads();
    }

#pragma unroll
    for (int mt = 0; mt < 4; mt++)
#pragma unroll
        for (int nt = 0; nt < 8; nt++) {
            const int row = mBase + wm + mt * 16 + lg;
            const int col = nl0 + wn + nt * 8 + 2 * t4;
            *(float2*)&C[(size_t)row * cN + col] =
                make_float2(acc[mt][nt][0], acc[mt][nt][1]);
            *(float2*)&C[(size_t)(row + 8) * cN + col] =
                make_float2(acc[mt][nt][2], acc[mt][nt][3]);
        }
}

// ---------------------------------------------------------------------------
// Flash attention: Br=128, Bc=64, 8 warps, 2-stage double-buffered K/V.
// Q resident in smem (fragments re-materialized via ldmatrix per k-slab).
// ---------------------------------------------------------------------------
#define BQ 128
#define BK 64
#define LDK 132
#define LDV 136
#define LDQS 132
#define KSTAGE (BK * LDK)
#define VSTAGE (BK * LDV)
#define ATTN_SMEM_FLOATS (BQ * LDQS + 2 * (KSTAGE + VSTAGE))  // 51200

__global__ __launch_bounds__(256, 1) void attn_mma(const float* __restrict__ q,
                                                   const float* __restrict__ k,
                                                   const float* __restrict__ v,
                                                   float* __restrict__ out) {
    extern __shared__ float sm[];
    float* Qstage = sm;                       // [BQ][LDQS], persistent
    float* KsB = sm + BQ * LDQS;              // 2 x [BK][LDK]
    float* VsB = KsB + 2 * KSTAGE;            // 2 x [BK][LDV]

    const int tid = threadIdx.x;
    const int w = tid >> 5;
    const int lane = tid & 31;
    const int lg = lane >> 2;
    const int t4 = lane & 3;

    const int qt = gridDim.x - 1 - blockIdx.x;   // heavy tiles first
    const int h = blockIdx.y;
    const int b = blockIdx.z;
    const int grp = h / (HEADS / GROUPS);
    const int qBase = qt * BQ;
    const int wq0 = w * 16;

    const float qscale = 0.08838834764831845f * 1.4426950408889634f;

    const int nkt = (qBase + BQ) / BK;   // >= 2
    const int ldrow = tid >> 5;          // 0..7
    const size_t kvcol = grp * HD + lane * 4;

    // ---- stage Q (scaled + tf32) ----
#pragma unroll
    for (int rnd = 0; rnd < 16; rnd++) {
        const int row = ldrow + rnd * 8;
        const float* qp = q + (size_t)(b * SEQ + qBase + row) * DM + h * HD +
                          lane * 4;
        float4 val = *(const float4*)qp;
        *(float4*)&Qstage[row * LDQS + lane * 4] =
            make_float4(__uint_as_float(f2tf(val.x * qscale)),
                        __uint_as_float(f2tf(val.y * qscale)),
                        __uint_as_float(f2tf(val.z * qscale)),
                        __uint_as_float(f2tf(val.w * qscale)));
    }

    // ---- prologue: tile0 -> stage0, prefetch tile1 into regs ----
    float4 pk[8], pv[8];
#pragma unroll
    for (int rnd = 0; rnd < 8; rnd++) {
        const size_t base = (size_t)(b * SEQ + rnd * 8 + ldrow) * DKV + kvcol;
        pk[rnd] = *(const float4*)(k + base);
        pv[rnd] = *(const float4*)(v + base);
    }
    {
        float* Ks = KsB;
        float* Vs = VsB;
#pragma unroll
        for (int rnd = 0; rnd < 8; rnd++) {
            const int row = ldrow + rnd * 8;
            float4 kv4 = pk[rnd];
            *(float4*)&Ks[row * LDK + lane * 4] =
                make_float4(__uint_as_float(f2tf(kv4.x)), __uint_as_float(f2tf(kv4.y)),
                            __uint_as_float(f2tf(kv4.z)), __uint_as_float(f2tf(kv4.w)));
            float4 vv4 = pv[rnd];
            *(float4*)&Vs[row * LDV + lane * 4] =
                make_float4(__uint_as_float(f2tf(vv4.x)), __uint_as_float(f2tf(vv4.y)),
                            __uint_as_float(f2tf(vv4.z)), __uint_as_float(f2tf(vv4.w)));
        }
    }
#pragma unroll
    for (int rnd = 0; rnd < 8; rnd++) {
        const size_t base = (size_t)(b * SEQ + BK + rnd * 8 + ldrow) * DKV + kvcol;
        pk[rnd] = *(const float4*)(k + base);
        pv[rnd] = *(const float4*)(v + base);
    }
    __syncthreads();   // Qstage + stage0 visible

    float oacc[16][4];
#pragma unroll
    for (int nt = 0; nt < 16; nt++)
#pragma unroll
        for (int i = 0; i < 4; i++) oacc[nt][i] = 0.f;

    float m0 = -1e30f, m1 = -1e30f, l0 = 0.f, l1 = 0.f;
    const int lastRow = qBase + wq0 + 15;
    const int row0g = qBase + wq0 + lg;

    const int kRow = ((lane >> 4) & 1) * 8 + (lane & 7);
    const int kCol = ((lane >> 3) & 1) * 4;
    const int qRow = wq0 + ((lane >> 3) & 1) * 8 + (lane & 7);
    const int qCol = (lane >> 4) * 4;

    for (int kt = 0; kt < nkt; kt++) {
        const int kBase = kt * BK;
        const float* Ks = KsB + (kt & 1) * KSTAGE;
        const float* Vs = VsB + (kt & 1) * VSTAGE;

        if (kBase <= lastRow) {
            // ---- phase A: S = Q K^T ----
            float sacc[8][4];
#pragma unroll
            for (int nt = 0; nt < 8; nt++)
#pragma unroll
                for (int i = 0; i < 4; i++) sacc[nt][i] = 0.f;

#pragma unroll
            for (int ks = 0; ks < 16; ks++) {
                const int k0 = ks * 8;
                unsigned qf[4];
                ldmx4(qf, &Qstage[qRow * LDQS + k0 + qCol]);
#pragma unroll
                for (int ntp = 0; ntp < 4; ntp++) {
                    unsigned bq[4];
                    ldmx4(bq, &Ks[(ntp * 16 + kRow) * LDK + k0 + kCol]);
                    mma8(sacc[2 * ntp], qf, bq);
                    mma8(sacc[2 * ntp + 1], qf, bq + 2);
                }
            }

            // ---- causal mask ----
            if (kBase + BK - 1 > qBase + wq0) {
#pragma unroll
                for (int nt = 0; nt < 8; nt++) {
                    const int c0 = kBase + nt * 8 + 2 * t4;
                    if (c0 > row0g) sacc[nt][0] = -1e30f;
                    if (c0 + 1 > row0g) sacc[nt][1] = -1e30f;
                    if (c0 > row0g + 8) sacc[nt][2] = -1e30f;
                    if (c0 + 1 > row0g + 8) sacc[nt][3] = -1e30f;
                }
            }

            // ---- online softmax (base-2), registers + quad shfl ----
            float mx0 = -1e30f, mx1 = -1e30f;
#pragma unroll
            for (int nt = 0; nt < 8; nt++) {
                mx0 = fmaxf(mx0, fmaxf(sacc[nt][0], sacc[nt][1]));
                mx1 = fmaxf(mx1, fmaxf(sacc[nt][2], sacc[nt][3]));
            }
            mx0 = fmaxf(mx0, __shfl_xor_sync(0xffffffff, mx0, 1));
            mx0 = fmaxf(mx0, __shfl_xor_sync(0xffffffff, mx0, 2));
            mx1 = fmaxf(mx1, __shfl_xor_sync(0xffffffff, mx1, 1));
            mx1 = fmaxf(mx1, __shfl_xor_sync(0xffffffff, mx1, 2));

            const float mn0 = fmaxf(m0, mx0);
            const float mn1 = fmaxf(m1, mx1);
            const float sc0 = fexp2(m0 - mn0);
            const float sc1 = fexp2(m1 - mn1);

            float sum0 = 0.f, sum1 = 0.f;
#pragma unroll
            for (int nt = 0; nt < 8; nt++) {
                float p0 = fexp2(sacc[nt][0] - mn0);
                float p1 = fexp2(sacc[nt][1] - mn0);
                float p2 = fexp2(sacc[nt][2] - mn1);
                float p3 = fexp2(sacc[nt][3] - mn1);
                sacc[nt][0] = p0; sacc[nt][1] = p1;
                sacc[nt][2] = p2; sacc[nt][3] = p3;
                sum0 += p0 + p1;
                sum1 += p2 + p3;
            }
            sum0 += __shfl_xor_sync(0xffffffff, sum0, 1);
            sum0 += __shfl_xor_sync(0xffffffff, sum0, 2);
            sum1 += __shfl_xor_sync(0xffffffff, sum1, 1);
            sum1 += __shfl_xor_sync(0xffffffff, sum1, 2);

            l0 = l0 * sc0 + sum0;  m0 = mn0;
            l1 = l1 * sc1 + sum1;  m1 = mn1;

#pragma unroll
            for (int nt = 0; nt < 16; nt++) {
                oacc[nt][0] *= sc0;
                oacc[nt][1] *= sc0;
                oacc[nt][2] *= sc1;
                oacc[nt][3] *= sc1;
            }

            // ---- phase C: O += P V ----
            const int srcA = (lane & 28) | (t4 >> 1);
            const int srcB = srcA + 2;
            const bool odd = (t4 & 1);
#pragma unroll
            for (int ks = 0; ks < 8; ks++) {
                const float v0 = sacc[ks][0], v1 = sacc[ks][1];
                const float v2 = sacc[ks][2], v3 = sacc[ks][3];
                float x0 = __shfl_sync(0xffffffff, v0, srcA);
                float x1 = __shfl_sync(0xffffffff, v1, srcA);
                float y0 = __shfl_sync(0xffffffff, v0, srcB);
                float y1 = __shfl_sync(0xffffffff, v1, srcB);
                float z0 = __shfl_sync(0xffffffff, v2, srcA);
                float z1 = __shfl_sync(0xffffffff, v3, srcA);
                float u0 = __shfl_sync(0xffffffff, v2, srcB);
                float u1 = __shfl_sync(0xffffffff, v3, srcB);
                unsigned pf[4];
                pf[0] = f2tf(odd ? x1 : x0);
                pf[1] = f2tf(odd ? z1 : z0);
                pf[2] = f2tf(odd ? y1 : y0);
                pf[3] = f2tf(odd ? u1 : u0);

                const int k0 = ks * 8;
#pragma unroll
                for (int nt = 0; nt < 16; nt++) {
                    unsigned bf[2];
                    bf[0] = __float_as_uint(Vs[(k0 + t4) * LDV + nt * 8 + lg]);
                    bf[1] = __float_as_uint(Vs[(k0 + t4 + 4) * LDV + nt * 8 + lg]);
                    mma8(oacc[nt], pf, bf);
                }
            }
        }

        // ---- pipeline: store prefetched tile kt+1, prefetch kt+2 ----
        if (kt + 1 < nkt) {
            float* Kn = KsB + ((kt + 1) & 1) * KSTAGE;
            float* Vn = VsB + ((kt + 1) & 1) * VSTAGE;
#pragma unroll
            for (int rnd = 0; rnd < 8; rnd++) {
                const int row = ldrow + rnd * 8;
                float4 kv4 = pk[rnd];
                *(float4*)&Kn[row * LDK + lane * 4] =
                    make_float4(__uint_as_float(f2tf(kv4.x)), __uint_as_float(f2tf(kv4.y)),
                                __uint_as_float(f2tf(kv4.z)), __uint_as_float(f2tf(kv4.w)));
                float4 vv4 = pv[rnd];
                *(float4*)&Vn[row * LDV + lane * 4] =
                    make_float4(__uint_as_float(f2tf(vv4.x)), __uint_as_float(f2tf(vv4.y)),
                                __uint_as_float(f2tf(vv4.z)), __uint_as_float(f2tf(vv4.w)));
            }
        }
        if (kt + 2 < nkt) {
            const int kb2 = (kt + 2) * BK;
#pragma unroll
            for (int rnd = 0; rnd < 8; rnd++) {
                const size_t base = (size_t)(b * SEQ + kb2 + rnd * 8 + ldrow) * DKV +
                                    kvcol;
                pk[rnd] = *(const float4*)(k + base);
                pv[rnd] = *(const float4*)(v + base);
            }
        }
        __syncthreads();
    }

    // ---- finalize + write ----
    const float inv0 = 1.0f / l0;
    const float inv1 = 1.0f / l1;
#pragma unroll
    for (int nt = 0; nt < 16; nt++) {
        const int d = h * HD + nt * 8 + 2 * t4;
        *(float2*)&out[(size_t)(b * SEQ + row0g) * DM + d] =
            make_float2(oacc[nt][0] * inv0, oacc[nt][1] * inv0);
        *(float2*)&out[(size_t)(b * SEQ + row0g + 8) * DM + d] =
            make_float2(oacc[nt][2] * inv1, oacc[nt][3] * inv1);
    }
}

// ---------------------------------------------------------------------------
extern "C" void kernel_launch(void* const* d_in, const int* in_sizes, int n_in,
                              void* d_out, int out_size) {
    const float* x = (const float*)d_in[0];
    const float* Wq = (const float*)d_in[1];
    const float* Wk = (const float*)d_in[2];
    const float* Wv = (const float*)d_in[3];
    float* out = (float*)d_out;

    float *pq = nullptr, *pk = nullptr, *pv = nullptr;
    cudaGetSymbolAddress((void**)&pq, g_q);
    cudaGetSymbolAddress((void**)&pk, g_k);
    cudaGetSymbolAddress((void**)&pv, g_v);

    static const size_t gemmSmem = GEMM_SMEM_FLOATS * sizeof(float);
    cudaFuncSetAttribute(gemm_qkv, cudaFuncAttributeMaxDynamicSharedMemorySize,
                         (int)gemmSmem);
    dim3 thr(256);
    dim3 gg(12, 32);
    gemm_qkv<<<gg, thr, gemmSmem>>>(x, Wq, Wk, Wv);

    static const size_t attnSmem = ATTN_SMEM_FLOATS * sizeof(float);
    cudaFuncSetAttribute(attn_mma, cudaFuncAttributeMaxDynamicSharedMemorySize,
                         (int)attnSmem);
    dim3 ga(SEQ / BQ, HEADS, BATCH);
    attn_mma<<<ga, thr, attnSmem>>>(pq, pk, pv, out);
}